// round 13
// baseline (speedup 1.0000x reference)
#include <cuda_runtime.h>
#include <cuda_fp16.h>

#define N_NODES 100000
#define N_EDGES 3200000
#define CAP 96                 // per-node bucket capacity (max degree ~60 for Poisson(32))

// ---------------- scratch ----------------
__device__ int      g_cnt[N_NODES];          // degree; re-zeroed by k_agg2f each replay
__device__ float    g_dinv[N_NODES];
__device__ int      g_bucket[N_NODES * CAP]; // per-node src lists
__device__ __half   g_x16[N_NODES * 32];     // x padded 22->32 fp16, scaled by dinv
__device__ float    g_aggX[N_NODES * 32];    // aggregated raw features (fp32)
__device__ __half   g_h16[N_NODES * 64];     // layer-2 agg input, pre-scaled by dinv

// ---------------- single edge pass: pad x, detect dtype, count+scatter ----------
__global__ void k_scatcnt(const float* __restrict__ x, const int* __restrict__ ei32) {
    __shared__ int s_is64;
    int t = threadIdx.x;
    if (t < 32) {   // per-block dtype detect (L2-broadcast reads, no cross-block race)
        int any = ei32[2 * t + 1] | ei32[2 * (t + 32) + 1];
        for (int off = 16; off; off >>= 1) any |= __shfl_xor_sync(0xffffffffu, any, off);
        if (t == 0) s_is64 = (any == 0) ? 1 : 0;
    }
    int i = blockIdx.x * blockDim.x + t;
    if (i < N_NODES * 32) {   // pad x -> x16 (unscaled; k_nodeprep scales)
        int n = i >> 5, c = i & 31;
        g_x16[i] = __float2half_rn((c < 22) ? x[n * 22 + c] : 0.f);
    }
    __syncthreads();
    int is64 = s_is64;
    int s = is64 ? ei32[2 * i] : ei32[i];
    int d = is64 ? ei32[2 * (N_EDGES + i)] : ei32[N_EDGES + i];
    if ((unsigned)d < N_NODES && (unsigned)s < N_NODES) {
        int pos = atomicAdd(&g_cnt[d], 1);
        if (pos < CAP) g_bucket[d * CAP + pos] = s;
    }
}

// ---------------- node pass: dinv + scale x16 (3.2M threads, 32 per node) -------
__global__ void k_nodeprep() {
    int i = blockIdx.x * blockDim.x + threadIdx.x;
    int n = i >> 5;
    float dn = rsqrtf((float)g_cnt[n] + 1.0f);   // +1 self-loop
    if ((i & 31) == 0) g_dinv[n] = dn;
    g_x16[i] = __float2half_rn(__half2float(g_x16[i]) * dn);
}

// aggX[d] = dinv[d]*(xs[d] + sum_e xs[src_e]).
// Warp per node; 8 lanes per edge (uint2 = 4 fp16 features), 4 edges per LDG.
__global__ void k_agg1() {
    int w = (blockIdx.x * blockDim.x + threadIdx.x) >> 5;
    int lane = threadIdx.x & 31;
    if (w >= N_NODES) return;
    float di = g_dinv[w];
    const uint2* __restrict__ x4 = (const uint2*)g_x16;   // 8 uint2 per node
    const int* __restrict__ bkt = g_bucket + w * CAP;
    int grp = lane >> 3, fl = lane & 7;
    float a0 = 0.f, a1 = 0.f, a2 = 0.f, a3 = 0.f;
    if (grp == 0) {   // self term once
        uint2 v = x4[w * 8 + fl];
        float2 f0 = __half22float2(*(__half2*)&v.x);
        float2 f1 = __half22float2(*(__half2*)&v.y);
        a0 = f0.x; a1 = f0.y; a2 = f1.x; a3 = f1.y;
    }
    int hi = min(g_cnt[w], CAP);
    int base = 0;
    int nfull = hi & ~31;
    for (; base < nfull; base += 32) {
        int sv = bkt[base + lane];
#pragma unroll
        for (int r = 0; r < 8; r++) {           // 8 rounds x 4 edges
            int sj = __shfl_sync(0xffffffffu, sv, r * 4 + grp);
            uint2 v = x4[sj * 8 + fl];
            float2 f0 = __half22float2(*(__half2*)&v.x);
            float2 f1 = __half22float2(*(__half2*)&v.y);
            a0 += f0.x; a1 += f0.y; a2 += f1.x; a3 += f1.y;
        }
    }
    int rem = hi - base;
    if (rem > 0) {
        int idx = base + lane;
        int sv = (idx < hi) ? bkt[idx] : 0;
        for (int j = 0; j < rem; j += 4) {
            int jj = j + grp;
            int sj = __shfl_sync(0xffffffffu, sv, (jj < rem) ? jj : 0);
            if (jj < rem) {
                uint2 v = x4[sj * 8 + fl];
                float2 f0 = __half22float2(*(__half2*)&v.x);
                float2 f1 = __half22float2(*(__half2*)&v.y);
                a0 += f0.x; a1 += f0.y; a2 += f1.x; a3 += f1.y;
            }
        }
    }
#pragma unroll
    for (int off = 8; off <= 16; off <<= 1) {
        a0 += __shfl_xor_sync(0xffffffffu, a0, off);
        a1 += __shfl_xor_sync(0xffffffffu, a1, off);
        a2 += __shfl_xor_sync(0xffffffffu, a2, off);
        a3 += __shfl_xor_sync(0xffffffffu, a3, off);
    }
    if (grp == 0) {
        float4 o = make_float4(di * a0, di * a1, di * a2, di * a3);
        ((float4*)g_aggX)[w * 8 + fl] = o;
    }
}

// h16 = fp16( dinv[node] * (relu(aggX@W1+b1)@W2) ); 32 nodes / 256-thread block
__global__ void k_xform12(const float* __restrict__ W1, const float* __restrict__ b1,
                          const float* __restrict__ W2) {
    __shared__ float W1s[22 * 64];
    __shared__ float W2s[64 * 64];
    __shared__ float h1s[4 * 64];
    __shared__ float as[4 * 22];
    int t = threadIdx.x;
    for (int i = t; i < 22 * 64; i += 256) W1s[i] = W1[i];
    for (int i = t; i < 64 * 64; i += 256) W2s[i] = W2[i];
    int r = t >> 6, j = t & 63;
    float b1j = b1[j];
#pragma unroll
    for (int p = 0; p < 8; p++) {
        int nb = blockIdx.x * 32 + p * 4;
        __syncthreads();
        for (int i = t; i < 4 * 22; i += 256) {
            int n = nb + i / 22;
            as[i] = (n < N_NODES) ? g_aggX[n * 32 + (i % 22)] : 0.f;
        }
        __syncthreads();
        float a = 0.f;
#pragma unroll
        for (int k = 0; k < 22; k++) a += as[r * 22 + k] * W1s[k * 64 + j];
        h1s[r * 64 + j] = fmaxf(a + b1j, 0.f);
        __syncthreads();
        float acc = 0.f;
#pragma unroll
        for (int k = 0; k < 64; k++) acc += h1s[r * 64 + k] * W2s[k * 64 + j];
        int node = nb + r;
        if (node < N_NODES)
            g_h16[node * 64 + j] = __float2half_rn(acc * g_dinv[node]);
    }
}

// layer-2 agg + head. Warp per node; 8 lanes per edge (uint4 = 8 fp16 features).
// Re-zeroes g_cnt (last reader) so the next graph replay starts clean.
__global__ void k_agg2f(const float* __restrict__ b2, const float* __restrict__ Wf,
                        const float* __restrict__ bf, float* __restrict__ out) {
    int w = (blockIdx.x * blockDim.x + threadIdx.x) >> 5;
    int lane = threadIdx.x & 31;
    if (w >= N_NODES) return;
    float di = g_dinv[w];
    const uint4* __restrict__ h4 = (const uint4*)g_h16;   // 8 uint4 per node
    const int* __restrict__ bkt = g_bucket + w * CAP;
    int grp = lane >> 3, fl = lane & 7;
    float a[8] = {0.f, 0.f, 0.f, 0.f, 0.f, 0.f, 0.f, 0.f};
    if (grp == 0) {
        uint4 v = h4[w * 8 + fl];
        float2 f0 = __half22float2(*(__half2*)&v.x);
        float2 f1 = __half22float2(*(__half2*)&v.y);
        float2 f2 = __half22float2(*(__half2*)&v.z);
        float2 f3 = __half22float2(*(__half2*)&v.w);
        a[0] = f0.x; a[1] = f0.y; a[2] = f1.x; a[3] = f1.y;
        a[4] = f2.x; a[5] = f2.y; a[6] = f3.x; a[7] = f3.y;
    }
    int hi = min(g_cnt[w], CAP);
    if (lane == 0) g_cnt[w] = 0;          // reset for next replay
    int base = 0;
    int nfull = hi & ~31;
    for (; base < nfull; base += 32) {
        int sv = bkt[base + lane];
#pragma unroll
        for (int r = 0; r < 8; r++) {
            int sj = __shfl_sync(0xffffffffu, sv, r * 4 + grp);
            uint4 v = h4[sj * 8 + fl];
            float2 f0 = __half22float2(*(__half2*)&v.x);
            float2 f1 = __half22float2(*(__half2*)&v.y);
            float2 f2 = __half22float2(*(__half2*)&v.z);
            float2 f3 = __half22float2(*(__half2*)&v.w);
            a[0] += f0.x; a[1] += f0.y; a[2] += f1.x; a[3] += f1.y;
            a[4] += f2.x; a[5] += f2.y; a[6] += f3.x; a[7] += f3.y;
        }
    }
    int rem = hi - base;
    if (rem > 0) {
        int idx = base + lane;
        int sv = (idx < hi) ? bkt[idx] : 0;
        for (int j = 0; j < rem; j += 4) {
            int jj = j + grp;
            int sj = __shfl_sync(0xffffffffu, sv, (jj < rem) ? jj : 0);
            if (jj < rem) {
                uint4 v = h4[sj * 8 + fl];
                float2 f0 = __half22float2(*(__half2*)&v.x);
                float2 f1 = __half22float2(*(__half2*)&v.y);
                float2 f2 = __half22float2(*(__half2*)&v.z);
                float2 f3 = __half22float2(*(__half2*)&v.w);
                a[0] += f0.x; a[1] += f0.y; a[2] += f1.x; a[3] += f1.y;
                a[4] += f2.x; a[5] += f2.y; a[6] += f3.x; a[7] += f3.y;
            }
        }
    }
#pragma unroll
    for (int off = 8; off <= 16; off <<= 1) {
#pragma unroll
        for (int k = 0; k < 8; k++) a[k] += __shfl_xor_sync(0xffffffffu, a[k], off);
    }
    float s = 0.f;
#pragma unroll
    for (int k = 0; k < 8; k++) {
        int f = fl * 8 + k;
        s += fmaxf(di * a[k] + b2[f], 0.f) * Wf[f];
    }
    s += __shfl_xor_sync(0xffffffffu, s, 1);
    s += __shfl_xor_sync(0xffffffffu, s, 2);
    s += __shfl_xor_sync(0xffffffffu, s, 4);
    if (lane == 0) out[w] = s + bf[0];
}

// ---------------- launch ----------------
extern "C" void kernel_launch(void* const* d_in, const int* in_sizes, int n_in,
                              void* d_out, int out_size) {
    const float* x   = (const float*)d_in[0];
    const int*   ei  = (const int*)d_in[1];
    const float* W1  = (const float*)d_in[2];
    const float* b1  = (const float*)d_in[3];
    const float* W2  = (const float*)d_in[4];
    const float* b2  = (const float*)d_in[5];
    const float* Wf  = (const float*)d_in[6];
    const float* bf  = (const float*)d_in[7];
    float* out = (float*)d_out;

    const int TB = 256;
    int gE = (N_EDGES + TB - 1) / TB;        // 12500 == N_NODES*32/256
    int gW = (N_NODES * 32 + TB - 1) / TB;
    int gT = (N_NODES + 31) / 32;

    k_scatcnt<<<gE, TB>>>(x, ei);            // single edge pass: count + bucket scatter
    k_nodeprep<<<gW, TB>>>();                // dinv + scale x16
    k_agg1<<<gW, TB>>>();
    k_xform12<<<gT, TB>>>(W1, b1, W2);
    k_agg2f<<<gW, TB>>>(b2, Wf, bf, out);    // also resets g_cnt
}

// round 14
// speedup vs baseline: 1.5764x; 1.5764x over previous
#include <cuda_runtime.h>
#include <cuda_fp16.h>

#define N_NODES 100000
#define N_EDGES 3200000
#define NB_SCAN 391            // ceil(N_NODES/256)

// ---------------- scratch ----------------
__device__ int      g_is64;
__device__ int      g_count[N_NODES];     // re-zeroed inside k_scanfused each run
__device__ int      g_ticket;             // re-zeroed by k_scatter for next replay
__device__ unsigned g_state[NB_SCAN];     // look-back {val<<2|status}; re-zeroed by k_scatter
__device__ int      g_off[N_NODES + 1];
__device__ int      g_cursor[N_NODES];
__device__ float    g_dinv[N_NODES];
__device__ int      g_src[N_EDGES];       // CSR src only (4B/edge)
__device__ __half   g_x16[N_NODES * 32];  // x padded 22->32 fp16, scaled by dinv
__device__ float    g_aggX[N_NODES * 32]; // aggregated raw features (fp32)
__device__ __half   g_h16[N_NODES * 64];  // layer-2 agg input, pre-scaled by dinv

// ---------------- fused init: pad x, detect dtype, count degrees ----------------
__global__ void k_initcount(const float* __restrict__ x, const int* __restrict__ ei32) {
    __shared__ int s_is64;
    int t = threadIdx.x;
    if (t < 32) {
        int any = ei32[2 * t + 1] | ei32[2 * (t + 32) + 1];
        for (int off = 16; off; off >>= 1) any |= __shfl_xor_sync(0xffffffffu, any, off);
        if (t == 0) {
            s_is64 = (any == 0) ? 1 : 0;
            if (blockIdx.x == 0) g_is64 = s_is64;
        }
    }
    int i = blockIdx.x * blockDim.x + t;
    if (i < N_NODES * 32) {
        int n = i >> 5, c = i & 31;
        g_x16[i] = __float2half_rn((c < 22) ? x[n * 22 + c] : 0.f);
    }
    __syncthreads();
    int is64 = s_is64;
    int d = is64 ? ei32[2 * (N_EDGES + i)] : ei32[N_EDGES + i];
    if ((unsigned)d < N_NODES) atomicAdd(&g_count[d], 1);
}

// ---------------- single-kernel decoupled look-back scan ----------------
__global__ void k_scanfused() {
    __shared__ int smbid;
    __shared__ int wsum[8];
    __shared__ int sprefix;
    int t = threadIdx.x;
    if (t == 0) smbid = atomicAdd(&g_ticket, 1);
    __syncthreads();
    int bid = smbid;
    int i = bid * 256 + t;
    int c = (i < N_NODES) ? g_count[i] : 0;
    if (i < N_NODES) {
        g_dinv[i] = rsqrtf((float)c + 1.0f);   // +1 self-loop
        g_count[i] = 0;
    }
    int lane = t & 31, wid = t >> 5;
    int s = c;
#pragma unroll
    for (int off = 1; off < 32; off <<= 1) {
        int u = __shfl_up_sync(0xffffffffu, s, off);
        if (lane >= off) s += u;
    }
    if (lane == 31) wsum[wid] = s;
    __syncthreads();
    if (wid == 0) {
        int ws = (lane < 8) ? wsum[lane] : 0;
#pragma unroll
        for (int off = 1; off < 8; off <<= 1) {
            int u = __shfl_up_sync(0xffffffffu, ws, off);
            if (lane >= off) ws += u;
        }
        if (lane < 8) wsum[lane] = ws;
    }
    __syncthreads();
    int incl = s + (wid ? wsum[wid - 1] : 0);
    int total = wsum[7];
    if (t == 0) {
        atomicExch(&g_state[bid], ((unsigned)total << 2) | 1u);
        int prefix = 0;
        for (int j = bid - 1; j >= 0;) {
            unsigned st = atomicAdd(&g_state[j], 0u);
            unsigned tag = st & 3u;
            if (tag == 2u) { prefix += (int)(st >> 2); break; }
            if (tag == 1u) { prefix += (int)(st >> 2); j--; }
        }
        atomicExch(&g_state[bid], ((unsigned)(prefix + total) << 2) | 2u);
        sprefix = prefix;
    }
    __syncthreads();
    int prefix = sprefix;
    if (i < N_NODES) {
        int excl = prefix + incl - c;
        g_off[i] = excl;
        g_cursor[i] = excl;
    }
    if (bid == NB_SCAN - 1 && t == 255) g_off[N_NODES] = prefix + incl;
}

// scatter + scale x16 by dinv + reset look-back state for next replay
__global__ void k_scatter(const int* __restrict__ ei32) {
    int e = blockIdx.x * blockDim.x + threadIdx.x;
    if (e < NB_SCAN) g_state[e] = 0u;
    if (e == NB_SCAN) g_ticket = 0;
    {
        float dn = g_dinv[e >> 5];
        g_x16[e] = __float2half_rn(__half2float(g_x16[e]) * dn);
    }
    int is64 = g_is64;
    int s = is64 ? ei32[2 * e] : ei32[e];
    int d = is64 ? ei32[2 * (N_EDGES + e)] : ei32[N_EDGES + e];
    if ((unsigned)d < N_NODES && (unsigned)s < N_NODES) {
        int pos = atomicAdd(&g_cursor[d], 1);
        g_src[pos] = s;
    }
}

// aggX[d] = dinv[d]*(xs[d] + sum_e xs[src_e]).
// Warp per node; 8 lanes per edge (uint2 = 4 fp16 features), 4 edges per LDG.
__global__ void k_agg1() {
    int w = (blockIdx.x * blockDim.x + threadIdx.x) >> 5;
    int lane = threadIdx.x & 31;
    if (w >= N_NODES) return;
    float di = g_dinv[w];
    const uint2* __restrict__ x4 = (const uint2*)g_x16;   // 8 uint2 per node
    int grp = lane >> 3, fl = lane & 7;
    float a0 = 0.f, a1 = 0.f, a2 = 0.f, a3 = 0.f;
    if (grp == 0) {   // self term once
        uint2 v = x4[w * 8 + fl];
        float2 f0 = __half22float2(*(__half2*)&v.x);
        float2 f1 = __half22float2(*(__half2*)&v.y);
        a0 = f0.x; a1 = f0.y; a2 = f1.x; a3 = f1.y;
    }
    int lo = g_off[w], hi = g_off[w + 1];
    int base = lo;
    int nfull = (hi - lo) & ~31;
    for (; base < lo + nfull; base += 32) {
        int sv = g_src[base + lane];
#pragma unroll
        for (int r = 0; r < 8; r++) {           // 8 rounds x 4 edges
            int sj = __shfl_sync(0xffffffffu, sv, r * 4 + grp);
            uint2 v = x4[sj * 8 + fl];
            float2 f0 = __half22float2(*(__half2*)&v.x);
            float2 f1 = __half22float2(*(__half2*)&v.y);
            a0 += f0.x; a1 += f0.y; a2 += f1.x; a3 += f1.y;
        }
    }
    int rem = hi - base;
    if (rem > 0) {
        int idx = base + lane;
        int sv = (idx < hi) ? g_src[idx] : 0;
        for (int j = 0; j < rem; j += 4) {
            int jj = j + grp;
            int sj = __shfl_sync(0xffffffffu, sv, (jj < rem) ? jj : 0);
            if (jj < rem) {
                uint2 v = x4[sj * 8 + fl];
                float2 f0 = __half22float2(*(__half2*)&v.x);
                float2 f1 = __half22float2(*(__half2*)&v.y);
                a0 += f0.x; a1 += f0.y; a2 += f1.x; a3 += f1.y;
            }
        }
    }
#pragma unroll
    for (int off = 8; off <= 16; off <<= 1) {
        a0 += __shfl_xor_sync(0xffffffffu, a0, off);
        a1 += __shfl_xor_sync(0xffffffffu, a1, off);
        a2 += __shfl_xor_sync(0xffffffffu, a2, off);
        a3 += __shfl_xor_sync(0xffffffffu, a3, off);
    }
    if (grp == 0) {
        float4 o = make_float4(di * a0, di * a1, di * a2, di * a3);
        ((float4*)g_aggX)[w * 8 + fl] = o;
    }
}

// ---------------- register-tiled transform ----------------
// h16 = fp16( dinv * (relu(aggX[:, :22]@W1 + b1) @ W2) )
// 64 nodes per 256-thread block; each thread computes a 4-node x 4-output tile.
__global__ void k_xform(const float* __restrict__ W1, const float* __restrict__ b1,
                        const float* __restrict__ W2) {
    __shared__ float W1s[22 * 64];
    __shared__ float W2s[64 * 64];
    __shared__ float as_t[22][68];    // transposed aggX tile (pad 68: float4-aligned rows)
    __shared__ float h1_t[64][68];    // transposed hidden tile
    int t = threadIdx.x;
    for (int i = t; i < 22 * 64; i += 256) W1s[i] = W1[i];
    for (int i = t; i < 64 * 64; i += 256) W2s[i] = W2[i];
    int nb = blockIdx.x * 64;
    for (int i = t; i < 64 * 32; i += 256) {      // coalesced global read, transpose in smem
        int n = i >> 5, c = i & 31;
        if (c < 22) {
            int node = nb + n;
            as_t[c][n] = (node < N_NODES) ? g_aggX[node * 32 + c] : 0.f;
        }
    }
    __syncthreads();

    int jt = t & 15, rt = t >> 4;     // 16 j-tiles x 16 r-tiles
    int j0 = jt * 4, r0 = rt * 4;

    float acc[4][4];
#pragma unroll
    for (int a = 0; a < 4; a++)
#pragma unroll
        for (int b = 0; b < 4; b++) acc[a][b] = 0.f;

#pragma unroll
    for (int k = 0; k < 22; k++) {
        float4 av = *(const float4*)&as_t[k][r0];
        float4 wv = *(const float4*)&W1s[k * 64 + j0];
        float ar[4] = {av.x, av.y, av.z, av.w};
        float wr[4] = {wv.x, wv.y, wv.z, wv.w};
#pragma unroll
        for (int a = 0; a < 4; a++)
#pragma unroll
            for (int b = 0; b < 4; b++) acc[a][b] += ar[a] * wr[b];
    }
    float bb[4] = {b1[j0], b1[j0 + 1], b1[j0 + 2], b1[j0 + 3]};
#pragma unroll
    for (int b = 0; b < 4; b++)
#pragma unroll
        for (int a = 0; a < 4; a++)
            h1_t[j0 + b][r0 + a] = fmaxf(acc[a][b] + bb[b], 0.f);
    __syncthreads();

#pragma unroll
    for (int a = 0; a < 4; a++)
#pragma unroll
        for (int b = 0; b < 4; b++) acc[a][b] = 0.f;
#pragma unroll
    for (int k = 0; k < 64; k++) {
        float4 av = *(const float4*)&h1_t[k][r0];
        float4 wv = *(const float4*)&W2s[k * 64 + j0];
        float ar[4] = {av.x, av.y, av.z, av.w};
        float wr[4] = {wv.x, wv.y, wv.z, wv.w};
#pragma unroll
        for (int a = 0; a < 4; a++)
#pragma unroll
            for (int b = 0; b < 4; b++) acc[a][b] += ar[a] * wr[b];
    }
#pragma unroll
    for (int a = 0; a < 4; a++) {
        int node = nb + r0 + a;
        if (node < N_NODES) {
            float dn = g_dinv[node];
            __half2* dst = (__half2*)&g_h16[node * 64 + j0];
            dst[0] = __floats2half2_rn(acc[a][0] * dn, acc[a][1] * dn);
            dst[1] = __floats2half2_rn(acc[a][2] * dn, acc[a][3] * dn);
        }
    }
}

// layer-2 agg + head. Warp per node; 8 lanes per edge (uint4 = 8 fp16 features).
__global__ void k_agg2f(const float* __restrict__ b2, const float* __restrict__ Wf,
                        const float* __restrict__ bf, float* __restrict__ out) {
    int w = (blockIdx.x * blockDim.x + threadIdx.x) >> 5;
    int lane = threadIdx.x & 31;
    if (w >= N_NODES) return;
    float di = g_dinv[w];
    const uint4* __restrict__ h4 = (const uint4*)g_h16;   // 8 uint4 per node
    int grp = lane >> 3, fl = lane & 7;
    float a[8] = {0.f, 0.f, 0.f, 0.f, 0.f, 0.f, 0.f, 0.f};
    if (grp == 0) {
        uint4 v = h4[w * 8 + fl];
        float2 f0 = __half22float2(*(__half2*)&v.x);
        float2 f1 = __half22float2(*(__half2*)&v.y);
        float2 f2 = __half22float2(*(__half2*)&v.z);
        float2 f3 = __half22float2(*(__half2*)&v.w);
        a[0] = f0.x; a[1] = f0.y; a[2] = f1.x; a[3] = f1.y;
        a[4] = f2.x; a[5] = f2.y; a[6] = f3.x; a[7] = f3.y;
    }
    int lo = g_off[w], hi = g_off[w + 1];
    int base = lo;
    int nfull = (hi - lo) & ~31;
    for (; base < lo + nfull; base += 32) {
        int sv = g_src[base + lane];
#pragma unroll
        for (int r = 0; r < 8; r++) {
            int sj = __shfl_sync(0xffffffffu, sv, r * 4 + grp);
            uint4 v = h4[sj * 8 + fl];
            float2 f0 = __half22float2(*(__half2*)&v.x);
            float2 f1 = __half22float2(*(__half2*)&v.y);
            float2 f2 = __half22float2(*(__half2*)&v.z);
            float2 f3 = __half22float2(*(__half2*)&v.w);
            a[0] += f0.x; a[1] += f0.y; a[2] += f1.x; a[3] += f1.y;
            a[4] += f2.x; a[5] += f2.y; a[6] += f3.x; a[7] += f3.y;
        }
    }
    int rem = hi - base;
    if (rem > 0) {
        int idx = base + lane;
        int sv = (idx < hi) ? g_src[idx] : 0;
        for (int j = 0; j < rem; j += 4) {
            int jj = j + grp;
            int sj = __shfl_sync(0xffffffffu, sv, (jj < rem) ? jj : 0);
            if (jj < rem) {
                uint4 v = h4[sj * 8 + fl];
                float2 f0 = __half22float2(*(__half2*)&v.x);
                float2 f1 = __half22float2(*(__half2*)&v.y);
                float2 f2 = __half22float2(*(__half2*)&v.z);
                float2 f3 = __half22float2(*(__half2*)&v.w);
                a[0] += f0.x; a[1] += f0.y; a[2] += f1.x; a[3] += f1.y;
                a[4] += f2.x; a[5] += f2.y; a[6] += f3.x; a[7] += f3.y;
            }
        }
    }
#pragma unroll
    for (int off = 8; off <= 16; off <<= 1) {
#pragma unroll
        for (int k = 0; k < 8; k++) a[k] += __shfl_xor_sync(0xffffffffu, a[k], off);
    }
    float s = 0.f;
#pragma unroll
    for (int k = 0; k < 8; k++) {
        int f = fl * 8 + k;
        s += fmaxf(di * a[k] + b2[f], 0.f) * Wf[f];
    }
    s += __shfl_xor_sync(0xffffffffu, s, 1);
    s += __shfl_xor_sync(0xffffffffu, s, 2);
    s += __shfl_xor_sync(0xffffffffu, s, 4);
    if (lane == 0) out[w] = s + bf[0];
}

// ---------------- launch ----------------
extern "C" void kernel_launch(void* const* d_in, const int* in_sizes, int n_in,
                              void* d_out, int out_size) {
    const float* x   = (const float*)d_in[0];
    const int*   ei  = (const int*)d_in[1];
    const float* W1  = (const float*)d_in[2];
    const float* b1  = (const float*)d_in[3];
    const float* W2  = (const float*)d_in[4];
    const float* b2  = (const float*)d_in[5];
    const float* Wf  = (const float*)d_in[6];
    const float* bf  = (const float*)d_in[7];
    float* out = (float*)d_out;

    const int TB = 256;
    int gE = (N_EDGES + TB - 1) / TB;        // 12500 == N_NODES*32/256
    int gW = (N_NODES * 32 + TB - 1) / TB;
    int gX = (N_NODES + 63) / 64;

    k_initcount<<<gE, TB>>>(x, ei);
    k_scanfused<<<NB_SCAN, 256>>>();
    k_scatter<<<gE, TB>>>(ei);
    k_agg1<<<gW, TB>>>();
    k_xform<<<gX, TB>>>(W1, b1, W2);
    k_agg2f<<<gW, TB>>>(b2, Wf, bf, out);
}